// round 3
// baseline (speedup 1.0000x reference)
#include <cuda_runtime.h>
#include <cuda_bf16.h>
#include <math.h>

// S4D kernel init:  out[h,l] = 2 * Re( sum_n Ccf[h,n] * exp(dtA[h,n] * l) )
// l = j*128 + i ;  out[h,j,i] = sum_n Px[n,j]*Qr[n,i] - Py[n,j]*Qi[n,i]
//
// Round-3: n split into 2 passes of 16 so sQ is 16KB (total smem ~25KB),
// raising residency from 5 to 7 blocks/SM (occupancy 25% -> ~44%) to hide
// LDS latency. Inner loop unchanged from round 2 (warp-uniform P broadcasts,
// packed fma.rn.f32x2 over j-pairs).

#define N2 32
#define NP 16          // n-rows per pass
#define TT 128
#define NTHREADS 128
#define NJ 32

typedef unsigned long long u64;

__device__ __forceinline__ u64 pack2(float x, float y) {
    u64 r; asm("mov.b64 %0, {%1, %2};" : "=l"(r) : "f"(x), "f"(y)); return r;
}
__device__ __forceinline__ u64 fma2(u64 a, u64 b, u64 c) {
    u64 d; asm("fma.rn.f32x2 %0, %1, %2, %3;" : "=l"(d) : "l"(a), "l"(b), "l"(c)); return d;
}
__device__ __forceinline__ float2 unpack2(u64 v) {
    float2 f; asm("mov.b64 {%0, %1}, %2;" : "=f"(f.x), "=f"(f.y) : "l"(v)); return f;
}

__global__ __launch_bounds__(NTHREADS, 7)
void s4d_vandermonde_kernel(
    const float* __restrict__ log_dt,
    const float* __restrict__ C,          // (H, N2, 2)
    const float* __restrict__ log_A_real, // (H, N2)
    const float* __restrict__ A_imag,     // (H, N2)
    float* __restrict__ out,              // (H, L)
    int L)
{
    __shared__ float2 sQ[NP][TT];       // 16 KB, reused across 2 passes
    __shared__ float  sPx[N2][NJ];      //  4 KB :  Re exp(dtA*128*j)
    __shared__ float  sPny[N2][NJ];     //  4 KB : -Im exp(dtA*128*j)
    __shared__ float2 sW[N2];           // exp(dtA)
    __shared__ float  sAr[N2], sAi[N2];
    __shared__ float2 sCcf[N2];

    const int h    = blockIdx.x;
    const int tid  = threadIdx.x;
    const int lane = tid & 31;
    const int jt   = tid >> 5;          // warp id = j-tile (8 j each)

    // ---------- Phase 0: per-(h,n) coefficients ----------
    if (tid < N2) {
        const int n = tid;
        const int g = h * N2 + n;
        float dt  = expf(log_dt[h]);
        float ar0 = -expf(log_A_real[g]);   // Re(A)
        float ai0 = A_imag[g];              // Im(A)
        float ar  = ar0 * dt;               // Re(dtA)
        float ai  = ai0 * dt;               // Im(dtA)
        float er  = expf(ar), s, c;
        sincosf(ai, &s, &c);
        float wr = er * c, wi = er * s;     // w = exp(dtA)
        sW[n]  = make_float2(wr, wi);
        sAr[n] = ar;
        sAi[n] = ai;
        // D = (exp(dtA) - 1) / A
        float Er = wr - 1.0f, Ei = wi;
        float inv = 1.0f / (ar0 * ar0 + ai0 * ai0);
        float Dr = (Er * ar0 + Ei * ai0) * inv;
        float Di = (Ei * ar0 - Er * ai0) * inv;
        // Ccf = 2 * Cc * D
        float cr = C[2 * g], ci = C[2 * g + 1];
        sCcf[n] = make_float2(2.0f * (cr * Dr - ci * Di),
                              2.0f * (cr * Di + ci * Dr));
    }
    __syncthreads();

    // ---------- Phase 2: P[n][j] = exp(dtA * 128 * j), SoA, -Py folded ----------
    #pragma unroll
    for (int r = 0; r < (N2 * NJ) / NTHREADS; r++) {
        int idx = r * NTHREADS + tid;
        int n = idx >> 5;
        int j = idx & 31;
        float x = (float)(TT * j);
        float e = expf(sAr[n] * x), s, c;
        sincosf(sAi[n] * x, &s, &c);
        sPx[n][j]  = e * c;
        sPny[n][j] = -e * s;
    }

    // ---------- Accumulators: acc[i][jp], lo = j=8*jt+2*jp, hi = +1 ----------
    u64 acc[4][4];
    #pragma unroll
    for (int a = 0; a < 4; a++)
        #pragma unroll
        for (int b = 0; b < 4; b++) acc[a][b] = 0ULL;

    #pragma unroll
    for (int pass = 0; pass < 2; pass++) {
        // ----- Q build for this pass: 16 rows, 8 segments of 16 each -----
        {
            const int nl  = tid >> 3;           // 0..15 local row
            const int n   = pass * NP + nl;     // global n
            const int seg = tid & 7;            // 0..7 -> i = 16*seg..
            float ar = sAr[n], ai = sAi[n];
            float x  = 16.0f * (float)seg;
            float e  = expf(ar * x), s, c;
            sincosf(ai * x, &s, &c);
            float zr0 = e * c, zi0 = e * s;     // exp(dtA * 16*seg)
            float2 cc = sCcf[n];
            float zr = cc.x * zr0 - cc.y * zi0; // Ccf * anchor
            float zi = cc.x * zi0 + cc.y * zr0;
            float2 w = sW[n];
            const int ibase = seg * 16;
            #pragma unroll
            for (int k = 0; k < 16; k++) {
                sQ[nl][ibase + k] = make_float2(zr, zi);
                float nzr = zr * w.x - zi * w.y;
                float nzi = zr * w.y + zi * w.x;
                zr = nzr; zi = nzi;
            }
        }
        __syncthreads();   // Q (and on pass 0, P) ready

        // ----- Mainloop over this pass's 16 n-rows -----
        const float* pxBase  = &sPx[pass * NP][jt * 8];
        const float* pnyBase = &sPny[pass * NP][jt * 8];

        #pragma unroll 4
        for (int m = 0; m < NP; m++) {
            float2 q0 = sQ[m][lane];
            float2 q1 = sQ[m][lane + 32];
            float2 q2 = sQ[m][lane + 64];
            float2 q3 = sQ[m][lane + 96];
            u64 qr[4] = { pack2(q0.x, q0.x), pack2(q1.x, q1.x),
                          pack2(q2.x, q2.x), pack2(q3.x, q3.x) };
            u64 qi[4] = { pack2(q0.y, q0.y), pack2(q1.y, q1.y),
                          pack2(q2.y, q2.y), pack2(q3.y, q3.y) };
            const u64* px  = (const u64*)(pxBase  + m * NJ);  // warp-uniform
            const u64* pny = (const u64*)(pnyBase + m * NJ);  // broadcasts
            #pragma unroll
            for (int jp = 0; jp < 4; jp++) {
                u64 pxv  = px[jp];
                u64 pnyv = pny[jp];
                #pragma unroll
                for (int i = 0; i < 4; i++) {
                    acc[i][jp] = fma2(pxv,  qr[i], acc[i][jp]);
                    acc[i][jp] = fma2(pnyv, qi[i], acc[i][jp]);
                }
            }
        }
        __syncthreads();   // done reading sQ before next pass overwrites
    }

    // ---------- Store: coalesced across lanes ----------
    float* outh = out + (size_t)h * (size_t)L + jt * 8 * TT;
    #pragma unroll
    for (int jp = 0; jp < 4; jp++) {
        #pragma unroll
        for (int i = 0; i < 4; i++) {
            float2 v = unpack2(acc[i][jp]);
            outh[(2 * jp + 0) * TT + lane + 32 * i] = v.x;
            outh[(2 * jp + 1) * TT + lane + 32 * i] = v.y;
        }
    }
}

extern "C" void kernel_launch(void* const* d_in, const int* in_sizes, int n_in,
                              void* d_out, int out_size) {
    // inputs: [0]=L (scalar), [1]=log_dt (H), [2]=C (H,N2,2),
    //         [3]=log_A_real (H,N2), [4]=A_imag (H,N2)
    const float* log_dt     = (const float*)d_in[1];
    const float* C          = (const float*)d_in[2];
    const float* log_A_real = (const float*)d_in[3];
    const float* A_imag     = (const float*)d_in[4];
    float* out = (float*)d_out;

    int H = in_sizes[1];          // 1024
    int L = out_size / H;         // 4096  (layout assumes L/128 = 32)

    s4d_vandermonde_kernel<<<H, NTHREADS>>>(log_dt, C, log_A_real, A_imag, out, L);
}

// round 4
// speedup vs baseline: 1.3756x; 1.3756x over previous
#include <cuda_runtime.h>
#include <cuda_bf16.h>
#include <math.h>

// S4D kernel init:  out[h,l] = 2 * Re( sum_n Ccf[h,n] * exp(dtA[h,n] * l) )
// l = j*128 + i ;  out[h,j,i] = sum_n Px[n,j]*Qr[n,i] - Py[n,j]*Qi[n,i]
//
// Round-4: Phase-1 STS bank conflicts eliminated (sQ rows padded to 129
// float2; recurrence lanes remapped so the n-row index is lane-fast).
// Mainloop unchanged: warp-uniform P broadcasts + packed fma.rn.f32x2.

#define N2 32
#define NP 16          // n-rows per pass
#define TT 128
#define TTP 129        // padded row (float2 units) -> bank stride 2 per row
#define NTHREADS 128
#define NJ 32

typedef unsigned long long u64;

__device__ __forceinline__ u64 pack2(float x, float y) {
    u64 r; asm("mov.b64 %0, {%1, %2};" : "=l"(r) : "f"(x), "f"(y)); return r;
}
__device__ __forceinline__ u64 fma2(u64 a, u64 b, u64 c) {
    u64 d; asm("fma.rn.f32x2 %0, %1, %2, %3;" : "=l"(d) : "l"(a), "l"(b), "l"(c)); return d;
}
__device__ __forceinline__ float2 unpack2(u64 v) {
    float2 f; asm("mov.b64 {%0, %1}, %2;" : "=f"(f.x), "=f"(f.y) : "l"(v)); return f;
}

__global__ __launch_bounds__(NTHREADS, 7)
void s4d_vandermonde_kernel(
    const float* __restrict__ log_dt,
    const float* __restrict__ C,          // (H, N2, 2)
    const float* __restrict__ log_A_real, // (H, N2)
    const float* __restrict__ A_imag,     // (H, N2)
    float* __restrict__ out,              // (H, L)
    int L)
{
    __shared__ float2 sQ[NP][TTP];      // 16.1 KB, padded, reused across passes
    __shared__ float  sPx[N2][NJ];      //  4 KB :  Re exp(dtA*128*j)
    __shared__ float  sPny[N2][NJ];     //  4 KB : -Im exp(dtA*128*j)
    __shared__ float2 sW[N2];           // exp(dtA)
    __shared__ float  sAr[N2], sAi[N2];
    __shared__ float2 sCcf[N2];

    const int h    = blockIdx.x;
    const int tid  = threadIdx.x;
    const int lane = tid & 31;
    const int jt   = tid >> 5;          // warp id = j-tile (8 j each)

    // ---------- Phase 0: per-(h,n) coefficients ----------
    if (tid < N2) {
        const int n = tid;
        const int g = h * N2 + n;
        float dt  = expf(log_dt[h]);
        float ar0 = -expf(log_A_real[g]);   // Re(A)
        float ai0 = A_imag[g];              // Im(A)
        float ar  = ar0 * dt;               // Re(dtA)
        float ai  = ai0 * dt;               // Im(dtA)
        float er  = expf(ar), s, c;
        sincosf(ai, &s, &c);
        float wr = er * c, wi = er * s;     // w = exp(dtA)
        sW[n]  = make_float2(wr, wi);
        sAr[n] = ar;
        sAi[n] = ai;
        // D = (exp(dtA) - 1) / A
        float Er = wr - 1.0f, Ei = wi;
        float inv = 1.0f / (ar0 * ar0 + ai0 * ai0);
        float Dr = (Er * ar0 + Ei * ai0) * inv;
        float Di = (Ei * ar0 - Er * ai0) * inv;
        // Ccf = 2 * Cc * D
        float cr = C[2 * g], ci = C[2 * g + 1];
        sCcf[n] = make_float2(2.0f * (cr * Dr - ci * Di),
                              2.0f * (cr * Di + ci * Dr));
    }
    __syncthreads();

    // ---------- Phase 2: P[n][j] = exp(dtA * 128 * j), SoA, -Py folded ----------
    #pragma unroll
    for (int r = 0; r < (N2 * NJ) / NTHREADS; r++) {
        int idx = r * NTHREADS + tid;
        int n = idx >> 5;
        int j = idx & 31;
        float x = (float)(TT * j);
        float e = expf(sAr[n] * x), s, c;
        sincosf(sAi[n] * x, &s, &c);
        sPx[n][j]  = e * c;
        sPny[n][j] = -e * s;
    }

    // ---------- Accumulators: acc[i][jp], lo = j=8*jt+2*jp, hi = +1 ----------
    u64 acc[4][4];
    #pragma unroll
    for (int a = 0; a < 4; a++)
        #pragma unroll
        for (int b = 0; b < 4; b++) acc[a][b] = 0ULL;

    #pragma unroll
    for (int pass = 0; pass < 2; pass++) {
        // ----- Q build: nl is LANE-FAST so STS lanes spread across banks -----
        {
            const int nl  = tid & 15;           // 0..15 local row (lane-fast)
            const int n   = pass * NP + nl;     // global n
            const int seg = tid >> 4;           // 0..7 -> i = 16*seg..
            float ar = sAr[n], ai = sAi[n];
            float x  = 16.0f * (float)seg;
            float e  = expf(ar * x), s, c;
            sincosf(ai * x, &s, &c);
            float zr0 = e * c, zi0 = e * s;     // exp(dtA * 16*seg)
            float2 cc = sCcf[n];
            float zr = cc.x * zr0 - cc.y * zi0; // Ccf * anchor
            float zi = cc.x * zi0 + cc.y * zr0;
            float2 w = sW[n];
            const int ibase = seg * 16;
            #pragma unroll
            for (int k = 0; k < 16; k++) {
                sQ[nl][ibase + k] = make_float2(zr, zi);
                float nzr = zr * w.x - zi * w.y;
                float nzi = zr * w.y + zi * w.x;
                zr = nzr; zi = nzi;
            }
        }
        __syncthreads();   // Q (and on pass 0, P) ready

        // ----- Mainloop over this pass's 16 n-rows -----
        const float* pxBase  = &sPx[pass * NP][jt * 8];
        const float* pnyBase = &sPny[pass * NP][jt * 8];

        #pragma unroll 4
        for (int m = 0; m < NP; m++) {
            float2 q0 = sQ[m][lane];
            float2 q1 = sQ[m][lane + 32];
            float2 q2 = sQ[m][lane + 64];
            float2 q3 = sQ[m][lane + 96];
            u64 qr[4] = { pack2(q0.x, q0.x), pack2(q1.x, q1.x),
                          pack2(q2.x, q2.x), pack2(q3.x, q3.x) };
            u64 qi[4] = { pack2(q0.y, q0.y), pack2(q1.y, q1.y),
                          pack2(q2.y, q2.y), pack2(q3.y, q3.y) };
            const u64* px  = (const u64*)(pxBase  + m * NJ);  // warp-uniform
            const u64* pny = (const u64*)(pnyBase + m * NJ);  // broadcasts
            #pragma unroll
            for (int jp = 0; jp < 4; jp++) {
                u64 pxv  = px[jp];
                u64 pnyv = pny[jp];
                #pragma unroll
                for (int i = 0; i < 4; i++) {
                    acc[i][jp] = fma2(pxv,  qr[i], acc[i][jp]);
                    acc[i][jp] = fma2(pnyv, qi[i], acc[i][jp]);
                }
            }
        }
        __syncthreads();   // done reading sQ before next pass overwrites
    }

    // ---------- Store: coalesced across lanes ----------
    float* outh = out + (size_t)h * (size_t)L + jt * 8 * TT;
    #pragma unroll
    for (int jp = 0; jp < 4; jp++) {
        #pragma unroll
        for (int i = 0; i < 4; i++) {
            float2 v = unpack2(acc[i][jp]);
            outh[(2 * jp + 0) * TT + lane + 32 * i] = v.x;
            outh[(2 * jp + 1) * TT + lane + 32 * i] = v.y;
        }
    }
}

extern "C" void kernel_launch(void* const* d_in, const int* in_sizes, int n_in,
                              void* d_out, int out_size) {
    // inputs: [0]=L (scalar), [1]=log_dt (H), [2]=C (H,N2,2),
    //         [3]=log_A_real (H,N2), [4]=A_imag (H,N2)
    const float* log_dt     = (const float*)d_in[1];
    const float* C          = (const float*)d_in[2];
    const float* log_A_real = (const float*)d_in[3];
    const float* A_imag     = (const float*)d_in[4];
    float* out = (float*)d_out;

    int H = in_sizes[1];          // 1024
    int L = out_size / H;         // 4096  (layout assumes L/128 = 32)

    s4d_vandermonde_kernel<<<H, NTHREADS>>>(log_dt, C, log_A_real, A_imag, out, L);
}